// round 2
// baseline (speedup 1.0000x reference)
#include <cuda_runtime.h>

#define BATCH 32
#define NP    4096          // N == M == 4096
#define TILE  2048          // candidates staged per SMEM tile (32 KB)
#define THREADS 256
#define BLK_PER (NP / THREADS)   // 16 blocks per (batch, direction)

// Scratch (allocation-free): preprocessed candidates and per-block partial sums.
// g_pre[w][b*NP + j] = (-2x, -2y, -2z, x^2+y^2+z^2) for point j of input w.
__device__ float4 g_pre[2][BATCH * NP];
__device__ float  g_part[2][BATCH][BLK_PER];

// ---------------------------------------------------------------------------
// Preprocess both clouds: raw (x,y,z) -> (-2x,-2y,-2z, ||c||^2)
// ---------------------------------------------------------------------------
__global__ void chamfer_pre_kernel(const float* __restrict__ x1,
                                   const float* __restrict__ x2) {
    int idx = blockIdx.x * blockDim.x + threadIdx.x;
    if (idx >= 2 * BATCH * NP) return;
    int which = idx / (BATCH * NP);
    int p     = idx - which * (BATCH * NP);
    const float* src = which ? x2 : x1;
    float x = src[3 * p + 0];
    float y = src[3 * p + 1];
    float z = src[3 * p + 2];
    g_pre[which][p] = make_float4(-2.0f * x, -2.0f * y, -2.0f * z,
                                  x * x + y * y + z * z);
}

// ---------------------------------------------------------------------------
// Main kernel: for each query point, min over all candidates of
//   v = cc - 2 q.c   (3 FFMA + 1 FMNMX per pair);  dist = ||q||^2 + min v
// Grid: (BLK_PER, BATCH, 2).  dir=0: queries=xyz1, candidates=xyz2.
// ---------------------------------------------------------------------------
__global__ void __launch_bounds__(THREADS)
chamfer_min_kernel(const float* __restrict__ x1, const float* __restrict__ x2) {
    __shared__ float4 sc[TILE];
    __shared__ float  red[THREADS / 32];

    const int dir = blockIdx.z;
    const int b   = blockIdx.y;
    const float*  qsrc = dir ? x2 : x1;
    const float4* cand = g_pre[dir ^ 1] + (size_t)b * NP;

    const int qi = blockIdx.x * THREADS + threadIdx.x;      // 0..NP-1
    const float* qp = qsrc + ((size_t)b * NP + qi) * 3;
    const float qx = qp[0], qy = qp[1], qz = qp[2];
    const float qq = qx * qx + qy * qy + qz * qz;

    const float INF = __int_as_float(0x7f800000);
    float m0 = INF, m1 = INF, m2 = INF, m3 = INF;

    for (int t = 0; t < NP; t += TILE) {
        __syncthreads();   // previous tile fully consumed
        #pragma unroll
        for (int j = threadIdx.x; j < TILE; j += THREADS)
            sc[j] = cand[t + j];
        __syncthreads();

        #pragma unroll 4
        for (int j = 0; j < TILE; j += 4) {
            float4 a = sc[j + 0];
            m0 = fminf(m0, fmaf(qx, a.x, fmaf(qy, a.y, fmaf(qz, a.z, a.w))));
            float4 c1 = sc[j + 1];
            m1 = fminf(m1, fmaf(qx, c1.x, fmaf(qy, c1.y, fmaf(qz, c1.z, c1.w))));
            float4 c2 = sc[j + 2];
            m2 = fminf(m2, fmaf(qx, c2.x, fmaf(qy, c2.y, fmaf(qz, c2.z, c2.w))));
            float4 c3 = sc[j + 3];
            m3 = fminf(m3, fmaf(qx, c3.x, fmaf(qy, c3.y, fmaf(qz, c3.z, c3.w))));
        }
    }

    float mv = fminf(fminf(m0, m1), fminf(m2, m3)) + qq;

    // Block-sum of per-query min distances (deterministic, no atomics).
    #pragma unroll
    for (int o = 16; o > 0; o >>= 1)
        mv += __shfl_xor_sync(0xffffffffu, mv, o);
    if ((threadIdx.x & 31) == 0)
        red[threadIdx.x >> 5] = mv;
    __syncthreads();
    if (threadIdx.x == 0) {
        float s = 0.0f;
        #pragma unroll
        for (int w = 0; w < THREADS / 32; w++) s += red[w];
        g_part[dir][b][blockIdx.x] = s;
    }
}

// ---------------------------------------------------------------------------
// Final reduce: out[b] = (sum_dir0 + sum_dir1) / NP   (N == M)
// ---------------------------------------------------------------------------
__global__ void chamfer_final_kernel(float* __restrict__ out) {
    int b = threadIdx.x;
    if (b < BATCH) {
        float s = 0.0f;
        #pragma unroll
        for (int d = 0; d < 2; d++)
            #pragma unroll
            for (int i = 0; i < BLK_PER; i++)
                s += g_part[d][b][i];
        out[b] = s * (1.0f / (float)NP);
    }
}

extern "C" void kernel_launch(void* const* d_in, const int* in_sizes, int n_in,
                              void* d_out, int out_size) {
    const float* x1 = (const float*)d_in[0];
    const float* x2 = (const float*)d_in[1];
    float* out = (float*)d_out;

    int total = 2 * BATCH * NP;
    chamfer_pre_kernel<<<(total + 255) / 256, 256>>>(x1, x2);
    chamfer_min_kernel<<<dim3(BLK_PER, BATCH, 2), THREADS>>>(x1, x2);
    chamfer_final_kernel<<<1, 32>>>(out);
}